// round 13
// baseline (speedup 1.0000x reference)
#include <cuda_runtime.h>
#include <cuda_bf16.h>
#include <stdint.h>

#define N_NODES 50000
#define F 256
#define NFEAT 1024
#define E_MAX 800000
#define EPSV 1e-5f
typedef __nv_bfloat16 BF16;

// ---------------- scratch (__device__ globals) ----------------
__device__ float g_h1  [(size_t)N_NODES * F];
__device__ float g_h2  [(size_t)N_NODES * F];
__device__ float g_agg2[(size_t)N_NODES * F];
__device__ BF16 g_xh[(size_t)N_NODES * NFEAT];
__device__ BF16 g_xl[(size_t)N_NODES * NFEAT];
__device__ BF16 g_a1h[(size_t)N_NODES * F];
__device__ BF16 g_a1l[(size_t)N_NODES * F];
__device__ BF16 g_w1h[NFEAT * F], g_w1l[NFEAT * F];
__device__ BF16 g_w2h[F * F],     g_w2l[F * F];
__device__ float g_deg [N_NODES];
__device__ float g_dinv[N_NODES];
__device__ int   g_counts [N_NODES];
__device__ int   g_offsets[N_NODES + 1];
__device__ int   g_cursor [N_NODES];
__device__ uint2 g_epack  [E_MAX];          // (src, norm-weight)
__device__ float g_bnsum[F];
__device__ float g_bnssq[F];
__device__ int   g_is64;

// ---------------- side stream for graph fork (host-side objects only) ----------------
static cudaStream_t g_s2;
static cudaEvent_t  g_evFork, g_evJoin;
namespace {
struct StreamInit {
    StreamInit() {
        cudaStreamCreateWithFlags(&g_s2, cudaStreamNonBlocking);
        cudaEventCreateWithFlags(&g_evFork, cudaEventDisableTiming);
        cudaEventCreateWithFlags(&g_evJoin, cudaEventDisableTiming);
    }
};
static StreamInit g_si;
}

// ---------------- zero counts/deg + edge_index dtype detection (merged) ----------------
__global__ void detect_zero(const int* ei32, int n_check, int n) {
    int i = blockIdx.x * blockDim.x + threadIdx.x;
    if (i < n) { g_counts[i] = 0; g_deg[i] = 1.0f; }   // self-loop weight 1
    if (blockIdx.x == 0) {
        __shared__ int bad;
        if (threadIdx.x == 0) bad = 0;
        __syncthreads();
        for (int k = threadIdx.x; k < n_check; k += blockDim.x)
            if (ei32[2 * k + 1] != 0) bad = 1;
        __syncthreads();
        if (threadIdx.x == 0) g_is64 = bad ? 0 : 1;
    }
}

__device__ __forceinline__ long ld_idx(const void* ei, long i) {
    return g_is64 ? (long)((const long long*)ei)[i] : (long)((const int*)ei)[i];
}

// ---------------- degree + CSR ----------------
__global__ void histo_deg(const void* ei, const float* w, long E) {
    long e = blockIdx.x * (long)blockDim.x + threadIdx.x;
    if (e >= E) return;
    long dst = ld_idx(ei, E + e);
    atomicAdd(&g_deg[dst], w[e]);
    atomicAdd(&g_counts[(int)dst], 1);
}

__global__ void compute_dinv(int n) {
    int i = blockIdx.x * blockDim.x + threadIdx.x;
    if (i < n) {
        float d = g_deg[i];
        g_dinv[i] = d > 0.0f ? rsqrtf(fmaxf(d, 1e-30f)) : 0.0f;
    }
}

__global__ __launch_bounds__(1024) void scan_offsets(int n) {
    __shared__ int ssum[1024];
    int t = threadIdx.x;
    int chunk = (n + 1023) / 1024;
    int beg = t * chunk, end = min(beg + chunk, n);
    int s = 0;
    for (int i = beg; i < end; i++) s += g_counts[i];
    ssum[t] = s;
    __syncthreads();
    for (int o = 1; o < 1024; o <<= 1) {
        int u = (t >= o) ? ssum[t - o] : 0;
        __syncthreads();
        ssum[t] += u;
        __syncthreads();
    }
    int run = ssum[t] - s;
    for (int i = beg; i < end; i++) {
        g_offsets[i] = run;
        g_cursor[i]  = run;
        run += g_counts[i];
    }
    if (t == 1023) g_offsets[n] = run;
}

__global__ void scatter_edges(const void* ei, const float* w, long E) {
    long e = blockIdx.x * (long)blockDim.x + threadIdx.x;
    if (e >= E) return;
    long src = ld_idx(ei, e);
    long dst = ld_idx(ei, E + e);
    float nw = g_dinv[src] * w[e] * g_dinv[dst];
    int pos = atomicAdd(&g_cursor[(int)dst], 1);
    g_epack[pos] = make_uint2((unsigned)src, __float_as_uint(nw));
}

// ---------------- fp32 -> bf16 hi/lo split ----------------
__device__ __forceinline__ unsigned pk(BF16 lo, BF16 hi) {
    __nv_bfloat162 t = __halves2bfloat162(lo, hi);
    return *reinterpret_cast<unsigned*>(&t);
}

__global__ void convert_split(const float* __restrict__ in,
                              BF16* __restrict__ hi, BF16* __restrict__ lo,
                              long n4) {
    long i = blockIdx.x * (long)blockDim.x + threadIdx.x;
    if (i >= n4) return;
    float4 v = ((const float4*)in)[i];
    BF16 h0 = __float2bfloat16_rn(v.x), h1 = __float2bfloat16_rn(v.y);
    BF16 h2 = __float2bfloat16_rn(v.z), h3 = __float2bfloat16_rn(v.w);
    BF16 l0 = __float2bfloat16_rn(v.x - __bfloat162float(h0));
    BF16 l1 = __float2bfloat16_rn(v.y - __bfloat162float(h1));
    BF16 l2 = __float2bfloat16_rn(v.z - __bfloat162float(h2));
    BF16 l3 = __float2bfloat16_rn(v.w - __bfloat162float(h3));
    ((uint2*)hi)[i] = make_uint2(pk(h0, h1), pk(h2, h3));
    ((uint2*)lo)[i] = make_uint2(pk(l0, l1), pk(l2, l3));
}

// ---------------- mma helpers ----------------
__device__ __forceinline__ uint32_t s2u(const void* p) {
    return (uint32_t)__cvta_generic_to_shared(p);
}

__device__ __forceinline__ void ldsm_x4(unsigned* r, const void* p) {
    unsigned a = (unsigned)__cvta_generic_to_shared(p);
    asm volatile("ldmatrix.sync.aligned.m8n8.x4.shared.b16 {%0,%1,%2,%3}, [%4];"
                 : "=r"(r[0]), "=r"(r[1]), "=r"(r[2]), "=r"(r[3]) : "r"(a));
}

__device__ __forceinline__ void ldsm_x4_t(unsigned* r, const void* p) {
    unsigned a = (unsigned)__cvta_generic_to_shared(p);
    asm volatile("ldmatrix.sync.aligned.m8n8.x4.trans.shared.b16 {%0,%1,%2,%3}, [%4];"
                 : "=r"(r[0]), "=r"(r[1]), "=r"(r[2]), "=r"(r[3]) : "r"(a));
}

__device__ __forceinline__ void mma_bf16(float* d, const unsigned* a, const unsigned* b) {
    asm volatile(
        "mma.sync.aligned.m16n8k16.row.col.f32.bf16.bf16.f32 "
        "{%0,%1,%2,%3}, {%4,%5,%6,%7}, {%8,%9}, {%0,%1,%2,%3};"
        : "+f"(d[0]), "+f"(d[1]), "+f"(d[2]), "+f"(d[3])
        : "r"(a[0]), "r"(a[1]), "r"(a[2]), "r"(a[3]), "r"(b[0]), "r"(b[1]));
}

__device__ __forceinline__ void cpa16(uint32_t dst, const void* src, int srcbytes) {
    asm volatile("cp.async.cg.shared.global [%0], [%1], 16, %2;"
                 :: "r"(dst), "l"(src), "r"(srcbytes));
}

#define CP_COMMIT() asm volatile("cp.async.commit_group;" ::: "memory")
#define CP_WAIT1()  asm volatile("cp.async.wait_group 1;" ::: "memory")

// ---------------- cp.async 3-stage tensor-core GEMM (bf16x3) ----------------
// Block tile 128x128x32, 256 threads, 2x4 warp grid with 64x32 warp tiles,
// 3 stages, 2 CTAs/SM via launch_bounds.
#define STAGE_BYTES 37888
#define GEMM_DSMEM  (3 * STAGE_BYTES)

__global__ __launch_bounds__(256, 2) void gemm_bf16x3(
    int M, int N, int K,
    const BF16* __restrict__ AH, const BF16* __restrict__ AL,
    const BF16* __restrict__ BH, const BF16* __restrict__ BL,
    float* __restrict__ H)
{
    extern __shared__ __align__(16) char dynsm[];
    const int tid = threadIdx.x, lane = tid & 31, warp = tid >> 5;
    const int wm = warp >> 2, wn = warp & 3;
    const int bRow = blockIdx.x, bCol = blockIdx.y;
    const int nk = K / 32;

    const int ar  = tid >> 1;
    const int ac0 = (tid & 1) * 2;
    const int br  = tid >> 3;
    const int bc0 = (tid & 7) * 2;

    const int gra  = bRow * 128 + ar;
    const int grac = min(gra, M - 1);
    const int asz  = (gra < M) ? 16 : 0;
    const char* gA  = (const char*)(AH + (size_t)grac * K);
    const char* gAl = (const char*)(AL + (size_t)grac * K);
    const char* gB  = (const char*)(BH + (size_t)br * N + bCol * 128);
    const char* gBl = (const char*)(BL + (size_t)br * N + bCol * 128);

    auto issue = [&](int kb, int s) {
        char* base = dynsm + s * STAGE_BYTES;
        const char* pa  = gA  + (size_t)kb * 64;
        const char* pal = gAl + (size_t)kb * 64;
        uint32_t sa  = s2u(base + ar * 80);
        uint32_t sal = s2u(base + 10240 + ar * 80);
        cpa16(sa  + ac0 * 16,       pa  + ac0 * 16,       asz);
        cpa16(sa  + (ac0 + 1) * 16, pa  + (ac0 + 1) * 16, asz);
        cpa16(sal + ac0 * 16,       pal + ac0 * 16,       asz);
        cpa16(sal + (ac0 + 1) * 16, pal + (ac0 + 1) * 16, asz);
        const char* pb  = gB  + (size_t)kb * 32 * N * 2;
        const char* pbl = gBl + (size_t)kb * 32 * N * 2;
        uint32_t sb  = s2u(base + 20480 + br * 272);
        uint32_t sbl = s2u(base + 29184 + br * 272);
        cpa16(sb  + bc0 * 16,       pb  + bc0 * 16,       16);
        cpa16(sb  + (bc0 + 1) * 16, pb  + (bc0 + 1) * 16, 16);
        cpa16(sbl + bc0 * 16,       pbl + bc0 * 16,       16);
        cpa16(sbl + (bc0 + 1) * 16, pbl + (bc0 + 1) * 16, 16);
    };

    float acc[4][4][4];
#pragma unroll
    for (int mi = 0; mi < 4; mi++)
#pragma unroll
        for (int nj = 0; nj < 4; nj++)
#pragma unroll
            for (int r = 0; r < 4; r++) acc[mi][nj][r] = 0.f;

    issue(0, 0); CP_COMMIT();
    if (nk > 1) issue(1, 1);
    CP_COMMIT();

    const int g8  = lane & 7;
    const int m01 = (lane >> 3) & 1;
    const int m23 = lane >> 4;

    for (int kb = 0; kb < nk; kb++) {
        const int s = kb % 3;
        CP_WAIT1();
        __syncthreads();

        unsigned short* Ahp = (unsigned short*)(dynsm + s * STAGE_BYTES);
        unsigned short* Alp = (unsigned short*)(dynsm + s * STAGE_BYTES + 10240);
        unsigned short* Bhp = (unsigned short*)(dynsm + s * STAGE_BYTES + 20480);
        unsigned short* Blp = (unsigned short*)(dynsm + s * STAGE_BYTES + 29184);

#pragma unroll
        for (int kk = 0; kk < 2; kk++) {
            const int k0 = kk * 16;
            unsigned aFh[4][4], aFl[4][4];
#pragma unroll
            for (int mi = 0; mi < 4; mi++) {
                int row = wm * 64 + mi * 16 + g8 + m01 * 8;
                int kof = k0 + m23 * 8;
                ldsm_x4(aFh[mi], &Ahp[row * 40 + kof]);
                ldsm_x4(aFl[mi], &Alp[row * 40 + kof]);
            }
#pragma unroll
            for (int bj = 0; bj < 2; bj++) {
                int krow = k0 + g8 + m01 * 8;
                int ncol = wn * 32 + bj * 16 + m23 * 8;
                unsigned bFh[2][2], bFl[2][2];
                unsigned t[4];
                ldsm_x4_t(t, &Bhp[krow * 136 + ncol]);
                bFh[0][0] = t[0]; bFh[0][1] = t[1];
                bFh[1][0] = t[2]; bFh[1][1] = t[3];
                ldsm_x4_t(t, &Blp[krow * 136 + ncol]);
                bFl[0][0] = t[0]; bFl[0][1] = t[1];
                bFl[1][0] = t[2]; bFl[1][1] = t[3];
#pragma unroll
                for (int mi = 0; mi < 4; mi++)
#pragma unroll
                    for (int q = 0; q < 2; q++) {
                        int nj = 2 * bj + q;
                        mma_bf16(acc[mi][nj], aFh[mi], bFh[q]);
                        mma_bf16(acc[mi][nj], aFh[mi], bFl[q]);
                        mma_bf16(acc[mi][nj], aFl[mi], bFh[q]);
                    }
            }
        }

        int nkb = kb + 2;
        if (nkb < nk) issue(nkb, nkb % 3);
        CP_COMMIT();
    }

    const int gg = lane >> 2, cc = lane & 3;
#pragma unroll
    for (int mi = 0; mi < 4; mi++) {
        int rb = bRow * 128 + wm * 64 + mi * 16;
        int r0 = rb + gg, r1 = rb + gg + 8;
#pragma unroll
        for (int nj = 0; nj < 4; nj++) {
            int col = bCol * 128 + wn * 32 + nj * 8 + 2 * cc;
            float* a = acc[mi][nj];
            if (r0 < M) *(float2*)(H + (size_t)r0 * N + col) = make_float2(a[0], a[1]);
            if (r1 < M) *(float2*)(H + (size_t)r1 * N + col) = make_float2(a[2], a[3]);
        }
    }
}

// ---------------- CSR gather aggregation (atomic-free, 2-edge unrolled) ----------------
template <int MODE>
__global__ __launch_bounds__(256) void gather_agg(
    const float* __restrict__ h, const float* __restrict__ bias,
    float* __restrict__ AGGF, BF16* __restrict__ AHo, BF16* __restrict__ ALo,
    int M)
{
    int warp = (blockIdx.x * blockDim.x + threadIdx.x) >> 5;
    int lane = threadIdx.x & 31;
    if (warp >= M) return;
    int dst = warp;
    int beg = g_offsets[dst], end = g_offsets[dst + 1];

    float4 s0a = make_float4(0.f, 0.f, 0.f, 0.f);
    float4 s0b = make_float4(0.f, 0.f, 0.f, 0.f);
    float4 s1a = make_float4(0.f, 0.f, 0.f, 0.f);
    float4 s1b = make_float4(0.f, 0.f, 0.f, 0.f);

    int e = beg;
    for (; e + 2 <= end; e += 2) {
        uint2 p0 = g_epack[e];
        uint2 p1 = g_epack[e + 1];
        float w0 = __uint_as_float(p0.y);
        float w1 = __uint_as_float(p1.y);
        const float4* q0 = (const float4*)(h + (size_t)p0.x * F);
        const float4* q1 = (const float4*)(h + (size_t)p1.x * F);
        float4 u00 = q0[lane], u01 = q0[lane + 32];
        float4 u10 = q1[lane], u11 = q1[lane + 32];
        s0a.x += w0 * u00.x; s0a.y += w0 * u00.y; s0a.z += w0 * u00.z; s0a.w += w0 * u00.w;
        s0b.x += w0 * u01.x; s0b.y += w0 * u01.y; s0b.z += w0 * u01.z; s0b.w += w0 * u01.w;
        s1a.x += w1 * u10.x; s1a.y += w1 * u10.y; s1a.z += w1 * u10.z; s1a.w += w1 * u10.w;
        s1b.x += w1 * u11.x; s1b.y += w1 * u11.y; s1b.z += w1 * u11.z; s1b.w += w1 * u11.w;
    }
    if (e < end) {
        uint2 p0 = g_epack[e];
        float w0 = __uint_as_float(p0.y);
        const float4* q0 = (const float4*)(h + (size_t)p0.x * F);
        float4 u00 = q0[lane], u01 = q0[lane + 32];
        s0a.x += w0 * u00.x; s0a.y += w0 * u00.y; s0a.z += w0 * u00.z; s0a.w += w0 * u00.w;
        s0b.x += w0 * u01.x; s0b.y += w0 * u01.y; s0b.z += w0 * u01.z; s0b.w += w0 * u01.w;
    }

    float di = g_dinv[dst], s = di * di;
    const float4* hd = (const float4*)(h + (size_t)dst * F);
    const float4* bp = (const float4*)bias;
    float4 u0 = hd[lane], u1 = hd[lane + 32];
    float4 b0 = bp[lane], b1 = bp[lane + 32];
    float4 o0, o1;
    o0.x = fmaxf(b0.x + s * u0.x + s0a.x + s1a.x, 0.f);
    o0.y = fmaxf(b0.y + s * u0.y + s0a.y + s1a.y, 0.f);
    o0.z = fmaxf(b0.z + s * u0.z + s0a.z + s1a.z, 0.f);
    o0.w = fmaxf(b0.w + s * u0.w + s0a.w + s1a.w, 0.f);
    o1.x = fmaxf(b1.x + s * u1.x + s0b.x + s1b.x, 0.f);
    o1.y = fmaxf(b1.y + s * u1.y + s0b.y + s1b.y, 0.f);
    o1.z = fmaxf(b1.z + s * u1.z + s0b.z + s1b.z, 0.f);
    o1.w = fmaxf(b1.w + s * u1.w + s0b.w + s1b.w, 0.f);

    if (MODE == 0) {
        float4* ap = (float4*)(AGGF + (size_t)dst * F);
        ap[lane] = o0;
        ap[lane + 32] = o1;
    } else {
        BF16 h0 = __float2bfloat16_rn(o0.x), h1 = __float2bfloat16_rn(o0.y);
        BF16 h2 = __float2bfloat16_rn(o0.z), h3 = __float2bfloat16_rn(o0.w);
        BF16 l0 = __float2bfloat16_rn(o0.x - __bfloat162float(h0));
        BF16 l1 = __float2bfloat16_rn(o0.y - __bfloat162float(h1));
        BF16 l2 = __float2bfloat16_rn(o0.z - __bfloat162float(h2));
        BF16 l3 = __float2bfloat16_rn(o0.w - __bfloat162float(h3));
        BF16 h4 = __float2bfloat16_rn(o1.x), h5 = __float2bfloat16_rn(o1.y);
        BF16 h6 = __float2bfloat16_rn(o1.z), h7 = __float2bfloat16_rn(o1.w);
        BF16 l4 = __float2bfloat16_rn(o1.x - __bfloat162float(h4));
        BF16 l5 = __float2bfloat16_rn(o1.y - __bfloat162float(h5));
        BF16 l6 = __float2bfloat16_rn(o1.z - __bfloat162float(h6));
        BF16 l7 = __float2bfloat16_rn(o1.w - __bfloat162float(h7));
        uint2* ph = (uint2*)(AHo + (size_t)dst * F);
        uint2* pl = (uint2*)(ALo + (size_t)dst * F);
        ph[lane]      = make_uint2(pk(h0, h1), pk(h2, h3));
        ph[lane + 32] = make_uint2(pk(h4, h5), pk(h6, h7));
        pl[lane]      = make_uint2(pk(l0, l1), pk(l2, l3));
        pl[lane + 32] = make_uint2(pk(l4, l5), pk(l6, l7));
    }
}

// ---------------- BN stats over agg2 (already relu'd) ----------------
__global__ void bn_zero() {
    int f = threadIdx.x;
    g_bnsum[f] = 0.0f;
    g_bnssq[f] = 0.0f;
}

__global__ void bn_stats(const float* __restrict__ agg2, int M, int rows_per_block) {
    int f = threadIdx.x;
    long r0 = blockIdx.x * (long)rows_per_block;
    long r1 = r0 + rows_per_block; if (r1 > M) r1 = M;
    float s = 0.f, ss = 0.f;
    for (long r = r0; r < r1; r++) {
        float v = agg2[r * F + f];
        s += v; ss += v * v;
    }
    atomicAdd(&g_bnsum[f], s);
    atomicAdd(&g_bnssq[f], ss);
}

// ---------------- fused BN + LN ----------------
__global__ void bn_ln_final(const float* __restrict__ agg2,
                            const float* __restrict__ bg, const float* __restrict__ bb,
                            const float* __restrict__ lg, const float* __restrict__ lb,
                            float* __restrict__ out, int M) {
    long r = blockIdx.x;
    int  f = threadIdx.x;
    int  lane = f & 31, wid = f >> 5;
    float invM = 1.0f / (float)M;

    float mu  = g_bnsum[f] * invM;
    float var = g_bnssq[f] * invM - mu * mu;
    float v = agg2[r * F + f];
    float y = (v - mu) * rsqrtf(var + EPSV) * bg[f] + bb[f];

    float s = y, ss = y * y;
#pragma unroll
    for (int o = 16; o > 0; o >>= 1) {
        s  += __shfl_xor_sync(0xffffffffu, s,  o);
        ss += __shfl_xor_sync(0xffffffffu, ss, o);
    }
    __shared__ float reds[8], redss[8];
    if (lane == 0) { reds[wid] = s; redss[wid] = ss; }
    __syncthreads();
    if (wid == 0) {
        float a = lane < 8 ? reds[lane]  : 0.f;
        float b = lane < 8 ? redss[lane] : 0.f;
#pragma unroll
        for (int o = 4; o > 0; o >>= 1) {
            a += __shfl_xor_sync(0xffffffffu, a, o);
            b += __shfl_xor_sync(0xffffffffu, b, o);
        }
        if (lane == 0) { reds[0] = a; redss[0] = b; }
    }
    __syncthreads();
    float lmu  = reds[0]  * (1.0f / F);
    float lvar = redss[0] * (1.0f / F) - lmu * lmu;
    out[r * F + f] = (y - lmu) * rsqrtf(lvar + EPSV) * lg[f] + lb[f];
}

// ---------------- launcher ----------------
extern "C" void kernel_launch(void* const* d_in, const int* in_sizes, int n_in,
                              void* d_out, int out_size) {
    const float* x  = (const float*)d_in[0];
    const void*  ei = d_in[1];
    const float* ew = (const float*)d_in[2];
    const float* W1 = (const float*)d_in[3];
    const float* b1 = (const float*)d_in[4];
    const float* W2 = (const float*)d_in[5];
    const float* b2 = (const float*)d_in[6];
    const float* bg = (const float*)d_in[7];
    const float* bb = (const float*)d_in[8];
    const float* lg = (const float*)d_in[9];
    const float* lb = (const float*)d_in[10];
    float* out = (float*)d_out;

    int  n = in_sizes[0] / NFEAT;            // 50000
    long E = in_sizes[1] / 2;                // 800000
    if (E > E_MAX) E = E_MAX;

    float* h1;   cudaGetSymbolAddress((void**)&h1,   g_h1);
    float* h2;   cudaGetSymbolAddress((void**)&h2,   g_h2);
    float* agg2; cudaGetSymbolAddress((void**)&agg2, g_agg2);
    BF16 *xh, *xl, *a1h, *a1l, *w1h, *w1l, *w2h, *w2l;
    cudaGetSymbolAddress((void**)&xh,  g_xh);
    cudaGetSymbolAddress((void**)&xl,  g_xl);
    cudaGetSymbolAddress((void**)&a1h, g_a1h);
    cudaGetSymbolAddress((void**)&a1l, g_a1l);
    cudaGetSymbolAddress((void**)&w1h, g_w1h);
    cudaGetSymbolAddress((void**)&w1l, g_w1l);
    cudaGetSymbolAddress((void**)&w2h, g_w2h);
    cudaGetSymbolAddress((void**)&w2l, g_w2l);

    cudaFuncSetAttribute(gemm_bf16x3,
                         cudaFuncAttributeMaxDynamicSharedMemorySize, GEMM_DSMEM);

    int eb = (int)((E + 255) / 256);
    long x4  = (long)n * NFEAT / 4;
    long w14 = (long)NFEAT * F / 4;
    long w24 = (long)F * F / 4;
    dim3 gg((n + 127) / 128, F / 128);
    int gatherBlocks = (n * 32 + 255) / 256;

    // ---- fork: CSR/degree chain runs on g_s2 concurrently with converts+GEMM1 ----
    cudaEventRecord(g_evFork, 0);
    cudaStreamWaitEvent(g_s2, g_evFork, 0);

    // legacy-stream launches 0-2: converts (gemm1 prereqs)
    convert_split<<<(int)((x4 + 255) / 256), 256>>>(x,  xh,  xl,  x4);
    convert_split<<<(int)((w14 + 255) / 256), 256>>>(W1, w1h, w1l, w14);
    convert_split<<<(int)((w24 + 255) / 256), 256>>>(W2, w2h, w2l, w24);

    // s2 launches 3-4 (host order; device-concurrent with legacy stream)
    detect_zero<<<(n + 255) / 256, 256, 0, g_s2>>>((const int*)ei, 1024, n);
    histo_deg<<<eb, 256, 0, g_s2>>>(ei, ew, E);

    // legacy launch 5: GEMM1 (ncu -s 5 capture slot)
    gemm_bf16x3<<<gg, 256, GEMM_DSMEM>>>(n, F, NFEAT, xh, xl, w1h, w1l, h1);

    // s2: rest of CSR chain + bn_zero
    compute_dinv<<<(n + 255) / 256, 256, 0, g_s2>>>(n);
    scan_offsets<<<1, 1024, 0, g_s2>>>(n);
    scatter_edges<<<eb, 256, 0, g_s2>>>(ei, ew, E);
    bn_zero<<<1, F, 0, g_s2>>>();
    cudaEventRecord(g_evJoin, g_s2);

    // ---- join: gather1 needs both GEMM1 (legacy) and CSR (s2) ----
    cudaStreamWaitEvent(0, g_evJoin, 0);
    gather_agg<1><<<gatherBlocks, 256>>>(h1, b1, nullptr, a1h, a1l, n);

    // ---- layer 2 ----
    gemm_bf16x3<<<gg, 256, GEMM_DSMEM>>>(n, F, F, a1h, a1l, w2h, w2l, h2);
    gather_agg<0><<<gatherBlocks, 256>>>(h2, b2, agg2, nullptr, nullptr, n);

    // ---- BN stats + fused BN/LN ----
    const int RPB = 128;
    bn_stats<<<(n + RPB - 1) / RPB, F>>>(agg2, n, RPB);
    bn_ln_final<<<n, F>>>(agg2, bg, bb, lg, lb, out, n);
}

// round 14
// speedup vs baseline: 1.0512x; 1.0512x over previous
#include <cuda_runtime.h>
#include <cuda_bf16.h>
#include <stdint.h>

#define N_NODES 50000
#define F 256
#define NFEAT 1024
#define E_MAX 800000
#define EPSV 1e-5f
typedef __nv_bfloat16 BF16;

// ---------------- scratch (__device__ globals) ----------------
__device__ float g_h1  [(size_t)N_NODES * F];
__device__ float g_h2  [(size_t)N_NODES * F];
__device__ float g_agg2[(size_t)N_NODES * F];
__device__ BF16 g_xh[(size_t)N_NODES * NFEAT];
__device__ BF16 g_xl[(size_t)N_NODES * NFEAT];
__device__ BF16 g_a1h[(size_t)N_NODES * F];
__device__ BF16 g_a1l[(size_t)N_NODES * F];
__device__ BF16 g_w1h[NFEAT * F], g_w1l[NFEAT * F];
__device__ BF16 g_w2h[F * F],     g_w2l[F * F];
__device__ float g_deg [N_NODES];
__device__ float g_dinv[N_NODES];
__device__ int   g_counts [N_NODES];
__device__ int   g_offsets[N_NODES + 1];
__device__ int   g_cursor [N_NODES];
__device__ uint2 g_epack  [E_MAX];          // (src, norm-weight)
__device__ float g_bnsum[F];
__device__ float g_bnssq[F];
__device__ int   g_is64;

// ---------------- zero counts/deg/bn + edge_index dtype detection (merged) ----------------
__global__ void detect_zero(const int* ei32, int n_check, int n) {
    int i = blockIdx.x * blockDim.x + threadIdx.x;
    if (i < n) { g_counts[i] = 0; g_deg[i] = 1.0f; }   // self-loop weight 1
    if (i < F) { g_bnsum[i] = 0.0f; g_bnssq[i] = 0.0f; }
    if (blockIdx.x == 0) {
        __shared__ int bad;
        if (threadIdx.x == 0) bad = 0;
        __syncthreads();
        for (int k = threadIdx.x; k < n_check; k += blockDim.x)
            if (ei32[2 * k + 1] != 0) bad = 1;
        __syncthreads();
        if (threadIdx.x == 0) g_is64 = bad ? 0 : 1;
    }
}

__device__ __forceinline__ long ld_idx(const void* ei, long i) {
    return g_is64 ? (long)((const long long*)ei)[i] : (long)((const int*)ei)[i];
}

// ---------------- degree + CSR ----------------
__global__ void histo_deg(const void* ei, const float* w, long E) {
    long e = blockIdx.x * (long)blockDim.x + threadIdx.x;
    if (e >= E) return;
    long dst = ld_idx(ei, E + e);
    atomicAdd(&g_deg[dst], w[e]);
    atomicAdd(&g_counts[(int)dst], 1);
}

// single block: dinv for all nodes + exclusive scan of counts -> offsets/cursor
__global__ __launch_bounds__(1024) void scan_offsets(int n) {
    __shared__ int ssum[1024];
    int t = threadIdx.x;
    // fused dinv (deg finalized by histo_deg)
    for (int i = t; i < n; i += 1024) {
        float d = g_deg[i];
        g_dinv[i] = d > 0.0f ? rsqrtf(fmaxf(d, 1e-30f)) : 0.0f;
    }
    int chunk = (n + 1023) / 1024;
    int beg = t * chunk, end = min(beg + chunk, n);
    int s = 0;
    for (int i = beg; i < end; i++) s += g_counts[i];
    ssum[t] = s;
    __syncthreads();
    for (int o = 1; o < 1024; o <<= 1) {
        int u = (t >= o) ? ssum[t - o] : 0;
        __syncthreads();
        ssum[t] += u;
        __syncthreads();
    }
    int run = ssum[t] - s;
    for (int i = beg; i < end; i++) {
        g_offsets[i] = run;
        g_cursor[i]  = run;
        run += g_counts[i];
    }
    if (t == 1023) g_offsets[n] = run;
}

__global__ void scatter_edges(const void* ei, const float* w, long E) {
    long e = blockIdx.x * (long)blockDim.x + threadIdx.x;
    if (e >= E) return;
    long src = ld_idx(ei, e);
    long dst = ld_idx(ei, E + e);
    float nw = g_dinv[src] * w[e] * g_dinv[dst];
    int pos = atomicAdd(&g_cursor[(int)dst], 1);
    g_epack[pos] = make_uint2((unsigned)src, __float_as_uint(nw));
}

// ---------------- fp32 -> bf16 hi/lo split ----------------
__device__ __forceinline__ unsigned pk(BF16 lo, BF16 hi) {
    __nv_bfloat162 t = __halves2bfloat162(lo, hi);
    return *reinterpret_cast<unsigned*>(&t);
}

__global__ void convert_split(const float* __restrict__ in,
                              BF16* __restrict__ hi, BF16* __restrict__ lo,
                              long n4) {
    long i = blockIdx.x * (long)blockDim.x + threadIdx.x;
    if (i >= n4) return;
    float4 v = ((const float4*)in)[i];
    BF16 h0 = __float2bfloat16_rn(v.x), h1 = __float2bfloat16_rn(v.y);
    BF16 h2 = __float2bfloat16_rn(v.z), h3 = __float2bfloat16_rn(v.w);
    BF16 l0 = __float2bfloat16_rn(v.x - __bfloat162float(h0));
    BF16 l1 = __float2bfloat16_rn(v.y - __bfloat162float(h1));
    BF16 l2 = __float2bfloat16_rn(v.z - __bfloat162float(h2));
    BF16 l3 = __float2bfloat16_rn(v.w - __bfloat162float(h3));
    ((uint2*)hi)[i] = make_uint2(pk(h0, h1), pk(h2, h3));
    ((uint2*)lo)[i] = make_uint2(pk(l0, l1), pk(l2, l3));
}

// ---------------- mma helpers ----------------
__device__ __forceinline__ uint32_t s2u(const void* p) {
    return (uint32_t)__cvta_generic_to_shared(p);
}

__device__ __forceinline__ void ldsm_x4(unsigned* r, const void* p) {
    unsigned a = (unsigned)__cvta_generic_to_shared(p);
    asm volatile("ldmatrix.sync.aligned.m8n8.x4.shared.b16 {%0,%1,%2,%3}, [%4];"
                 : "=r"(r[0]), "=r"(r[1]), "=r"(r[2]), "=r"(r[3]) : "r"(a));
}

__device__ __forceinline__ void ldsm_x4_t(unsigned* r, const void* p) {
    unsigned a = (unsigned)__cvta_generic_to_shared(p);
    asm volatile("ldmatrix.sync.aligned.m8n8.x4.trans.shared.b16 {%0,%1,%2,%3}, [%4];"
                 : "=r"(r[0]), "=r"(r[1]), "=r"(r[2]), "=r"(r[3]) : "r"(a));
}

__device__ __forceinline__ void mma_bf16(float* d, const unsigned* a, const unsigned* b) {
    asm volatile(
        "mma.sync.aligned.m16n8k16.row.col.f32.bf16.bf16.f32 "
        "{%0,%1,%2,%3}, {%4,%5,%6,%7}, {%8,%9}, {%0,%1,%2,%3};"
        : "+f"(d[0]), "+f"(d[1]), "+f"(d[2]), "+f"(d[3])
        : "r"(a[0]), "r"(a[1]), "r"(a[2]), "r"(a[3]), "r"(b[0]), "r"(b[1]));
}

__device__ __forceinline__ void cpa16(uint32_t dst, const void* src, int srcbytes) {
    asm volatile("cp.async.cg.shared.global [%0], [%1], 16, %2;"
                 :: "r"(dst), "l"(src), "r"(srcbytes));
}

#define CP_COMMIT() asm volatile("cp.async.commit_group;" ::: "memory")
#define CP_WAIT1()  asm volatile("cp.async.wait_group 1;" ::: "memory")

// ---------------- cp.async 3-stage tensor-core GEMM (bf16x3) ----------------
// Block tile 128x128x32, 256 threads, 2x4 warp grid with 64x32 warp tiles,
// 3 stages, 2 CTAs/SM via launch_bounds. (round-12 proven config)
#define STAGE_BYTES 37888
#define GEMM_DSMEM  (3 * STAGE_BYTES)

__global__ __launch_bounds__(256, 2) void gemm_bf16x3(
    int M, int N, int K,
    const BF16* __restrict__ AH, const BF16* __restrict__ AL,
    const BF16* __restrict__ BH, const BF16* __restrict__ BL,
    float* __restrict__ H)
{
    extern __shared__ __align__(16) char dynsm[];
    const int tid = threadIdx.x, lane = tid & 31, warp = tid >> 5;
    const int wm = warp >> 2, wn = warp & 3;
    const int bRow = blockIdx.x, bCol = blockIdx.y;
    const int nk = K / 32;

    const int ar  = tid >> 1;
    const int ac0 = (tid & 1) * 2;
    const int br  = tid >> 3;
    const int bc0 = (tid & 7) * 2;

    const int gra  = bRow * 128 + ar;
    const int grac = min(gra, M - 1);
    const int asz  = (gra < M) ? 16 : 0;
    const char* gA  = (const char*)(AH + (size_t)grac * K);
    const char* gAl = (const char*)(AL + (size_t)grac * K);
    const char* gB  = (const char*)(BH + (size_t)br * N + bCol * 128);
    const char* gBl = (const char*)(BL + (size_t)br * N + bCol * 128);

    auto issue = [&](int kb, int s) {
        char* base = dynsm + s * STAGE_BYTES;
        const char* pa  = gA  + (size_t)kb * 64;
        const char* pal = gAl + (size_t)kb * 64;
        uint32_t sa  = s2u(base + ar * 80);
        uint32_t sal = s2u(base + 10240 + ar * 80);
        cpa16(sa  + ac0 * 16,       pa  + ac0 * 16,       asz);
        cpa16(sa  + (ac0 + 1) * 16, pa  + (ac0 + 1) * 16, asz);
        cpa16(sal + ac0 * 16,       pal + ac0 * 16,       asz);
        cpa16(sal + (ac0 + 1) * 16, pal + (ac0 + 1) * 16, asz);
        const char* pb  = gB  + (size_t)kb * 32 * N * 2;
        const char* pbl = gBl + (size_t)kb * 32 * N * 2;
        uint32_t sb  = s2u(base + 20480 + br * 272);
        uint32_t sbl = s2u(base + 29184 + br * 272);
        cpa16(sb  + bc0 * 16,       pb  + bc0 * 16,       16);
        cpa16(sb  + (bc0 + 1) * 16, pb  + (bc0 + 1) * 16, 16);
        cpa16(sbl + bc0 * 16,       pbl + bc0 * 16,       16);
        cpa16(sbl + (bc0 + 1) * 16, pbl + (bc0 + 1) * 16, 16);
    };

    float acc[4][4][4];
#pragma unroll
    for (int mi = 0; mi < 4; mi++)
#pragma unroll
        for (int nj = 0; nj < 4; nj++)
#pragma unroll
            for (int r = 0; r < 4; r++) acc[mi][nj][r] = 0.f;

    issue(0, 0); CP_COMMIT();
    if (nk > 1) issue(1, 1);
    CP_COMMIT();

    const int g8  = lane & 7;
    const int m01 = (lane >> 3) & 1;
    const int m23 = lane >> 4;

    for (int kb = 0; kb < nk; kb++) {
        const int s = kb % 3;
        CP_WAIT1();
        __syncthreads();

        unsigned short* Ahp = (unsigned short*)(dynsm + s * STAGE_BYTES);
        unsigned short* Alp = (unsigned short*)(dynsm + s * STAGE_BYTES + 10240);
        unsigned short* Bhp = (unsigned short*)(dynsm + s * STAGE_BYTES + 20480);
        unsigned short* Blp = (unsigned short*)(dynsm + s * STAGE_BYTES + 29184);

#pragma unroll
        for (int kk = 0; kk < 2; kk++) {
            const int k0 = kk * 16;
            unsigned aFh[4][4], aFl[4][4];
#pragma unroll
            for (int mi = 0; mi < 4; mi++) {
                int row = wm * 64 + mi * 16 + g8 + m01 * 8;
                int kof = k0 + m23 * 8;
                ldsm_x4(aFh[mi], &Ahp[row * 40 + kof]);
                ldsm_x4(aFl[mi], &Alp[row * 40 + kof]);
            }
#pragma unroll
            for (int bj = 0; bj < 2; bj++) {
                int krow = k0 + g8 + m01 * 8;
                int ncol = wn * 32 + bj * 16 + m23 * 8;
                unsigned bFh[2][2], bFl[2][2];
                unsigned t[4];
                ldsm_x4_t(t, &Bhp[krow * 136 + ncol]);
                bFh[0][0] = t[0]; bFh[0][1] = t[1];
                bFh[1][0] = t[2]; bFh[1][1] = t[3];
                ldsm_x4_t(t, &Blp[krow * 136 + ncol]);
                bFl[0][0] = t[0]; bFl[0][1] = t[1];
                bFl[1][0] = t[2]; bFl[1][1] = t[3];
#pragma unroll
                for (int mi = 0; mi < 4; mi++)
#pragma unroll
                    for (int q = 0; q < 2; q++) {
                        int nj = 2 * bj + q;
                        mma_bf16(acc[mi][nj], aFh[mi], bFh[q]);
                        mma_bf16(acc[mi][nj], aFh[mi], bFl[q]);
                        mma_bf16(acc[mi][nj], aFl[mi], bFh[q]);
                    }
            }
        }

        int nkb = kb + 2;
        if (nkb < nk) issue(nkb, nkb % 3);
        CP_COMMIT();
    }

    const int gg = lane >> 2, cc = lane & 3;
#pragma unroll
    for (int mi = 0; mi < 4; mi++) {
        int rb = bRow * 128 + wm * 64 + mi * 16;
        int r0 = rb + gg, r1 = rb + gg + 8;
#pragma unroll
        for (int nj = 0; nj < 4; nj++) {
            int col = bCol * 128 + wn * 32 + nj * 8 + 2 * cc;
            float* a = acc[mi][nj];
            if (r0 < M) *(float2*)(H + (size_t)r0 * N + col) = make_float2(a[0], a[1]);
            if (r1 < M) *(float2*)(H + (size_t)r1 * N + col) = make_float2(a[2], a[3]);
        }
    }
}

// ---------------- CSR gather aggregation (atomic-free, 4-edge unrolled) ----------------
template <int MODE>
__global__ __launch_bounds__(256) void gather_agg(
    const float* __restrict__ h, const float* __restrict__ bias,
    float* __restrict__ AGGF, BF16* __restrict__ AHo, BF16* __restrict__ ALo,
    int M)
{
    int warp = (blockIdx.x * blockDim.x + threadIdx.x) >> 5;
    int lane = threadIdx.x & 31;
    if (warp >= M) return;
    int dst = warp;
    int beg = g_offsets[dst], end = g_offsets[dst + 1];

    float4 s0a = make_float4(0.f, 0.f, 0.f, 0.f);
    float4 s0b = make_float4(0.f, 0.f, 0.f, 0.f);
    float4 s1a = make_float4(0.f, 0.f, 0.f, 0.f);
    float4 s1b = make_float4(0.f, 0.f, 0.f, 0.f);

    int e = beg;
    for (; e + 4 <= end; e += 4) {
        uint2 p0 = g_epack[e];
        uint2 p1 = g_epack[e + 1];
        uint2 p2 = g_epack[e + 2];
        uint2 p3 = g_epack[e + 3];
        float w0 = __uint_as_float(p0.y);
        float w1 = __uint_as_float(p1.y);
        float w2 = __uint_as_float(p2.y);
        float w3 = __uint_as_float(p3.y);
        const float4* q0 = (const float4*)(h + (size_t)p0.x * F);
        const float4* q1 = (const float4*)(h + (size_t)p1.x * F);
        const float4* q2 = (const float4*)(h + (size_t)p2.x * F);
        const float4* q3 = (const float4*)(h + (size_t)p3.x * F);
        float4 u00 = q0[lane], u01 = q0[lane + 32];
        float4 u10 = q1[lane], u11 = q1[lane + 32];
        float4 u20 = q2[lane], u21 = q2[lane + 32];
        float4 u30 = q3[lane], u31 = q3[lane + 32];
        s0a.x += w0 * u00.x; s0a.y += w0 * u00.y; s0a.z += w0 * u00.z; s0a.w += w0 * u00.w;
        s0b.x += w0 * u01.x; s0b.y += w0 * u01.y; s0b.z += w0 * u01.z; s0b.w += w0 * u01.w;
        s1a.x += w1 * u10.x; s1a.y += w1 * u10.y; s1a.z += w1 * u10.z; s1a.w += w1 * u10.w;
        s1b.x += w1 * u11.x; s1b.y += w1 * u11.y; s1b.z += w1 * u11.z; s1b.w += w1 * u11.w;
        s0a.x += w2 * u20.x; s0a.y += w2 * u20.y; s0a.z += w2 * u20.z; s0a.w += w2 * u20.w;
        s0b.x += w2 * u21.x; s0b.y += w2 * u21.y; s0b.z += w2 * u21.z; s0b.w += w2 * u21.w;
        s1a.x += w3 * u30.x; s1a.y += w3 * u30.y; s1a.z += w3 * u30.z; s1a.w += w3 * u30.w;
        s1b.x += w3 * u31.x; s1b.y += w3 * u31.y; s1b.z += w3 * u31.z; s1b.w += w3 * u31.w;
    }
    for (; e < end; e++) {
        uint2 p0 = g_epack[e];
        float w0 = __uint_as_float(p0.y);
        const float4* q0 = (const float4*)(h + (size_t)p0.x * F);
        float4 u00 = q0[lane], u01 = q0[lane + 32];
        s0a.x += w0 * u00.x; s0a.y += w0 * u00.y; s0a.z += w0 * u00.z; s0a.w += w0 * u00.w;
        s0b.x += w0 * u01.x; s0b.y += w0 * u01.y; s0b.z += w0 * u01.z; s0b.w += w0 * u01.w;
    }

    float di = g_dinv[dst], s = di * di;
    const float4* hd = (const float4*)(h + (size_t)dst * F);
    const float4* bp = (const float4*)bias;
    float4 u0 = hd[lane], u1 = hd[lane + 32];
    float4 b0 = bp[lane], b1 = bp[lane + 32];
    float4 o0, o1;
    o0.x = fmaxf(b0.x + s * u0.x + s0a.x + s1a.x, 0.f);
    o0.y = fmaxf(b0.y + s * u0.y + s0a.y + s1a.y, 0.f);
    o0.z = fmaxf(b0.z + s * u0.z + s0a.z + s1a.z, 0.f);
    o0.w = fmaxf(b0.w + s * u0.w + s0a.w + s1a.w, 0.f);
    o1.x = fmaxf(b1.x + s * u1.x + s0b.x + s1b.x, 0.f);
    o1.y = fmaxf(b1.y + s * u1.y + s0b.y + s1b.y, 0.f);
    o1.z = fmaxf(b1.z + s * u1.z + s0b.z + s1b.z, 0.f);
    o1.w = fmaxf(b1.w + s * u1.w + s0b.w + s1b.w, 0.f);

    if (MODE == 0) {
        float4* ap = (float4*)(AGGF + (size_t)dst * F);
        ap[lane] = o0;
        ap[lane + 32] = o1;
    } else {
        BF16 h0 = __float2bfloat16_rn(o0.x), h1 = __float2bfloat16_rn(o0.y);
        BF16 h2 = __float2bfloat16_rn(o0.z), h3 = __float2bfloat16_rn(o0.w);
        BF16 l0 = __float2bfloat16_rn(o0.x - __bfloat162float(h0));
        BF16 l1 = __float2bfloat16_rn(o0.y - __bfloat162float(h1));
        BF16 l2 = __float2bfloat16_rn(o0.z - __bfloat162float(h2));
        BF16 l3 = __float2bfloat16_rn(o0.w - __bfloat162float(h3));
        BF16 h4 = __float2bfloat16_rn(o1.x), h5 = __float2bfloat16_rn(o1.y);
        BF16 h6 = __float2bfloat16_rn(o1.z), h7 = __float2bfloat16_rn(o1.w);
        BF16 l4 = __float2bfloat16_rn(o1.x - __bfloat162float(h4));
        BF16 l5 = __float2bfloat16_rn(o1.y - __bfloat162float(h5));
        BF16 l6 = __float2bfloat16_rn(o1.z - __bfloat162float(h6));
        BF16 l7 = __float2bfloat16_rn(o1.w - __bfloat162float(h7));
        uint2* ph = (uint2*)(AHo + (size_t)dst * F);
        uint2* pl = (uint2*)(ALo + (size_t)dst * F);
        ph[lane]      = make_uint2(pk(h0, h1), pk(h2, h3));
        ph[lane + 32] = make_uint2(pk(h4, h5), pk(h6, h7));
        pl[lane]      = make_uint2(pk(l0, l1), pk(l2, l3));
        pl[lane + 32] = make_uint2(pk(l4, l5), pk(l6, l7));
    }
}

// ---------------- BN stats over agg2 (already relu'd) ----------------
__global__ void bn_stats(const float* __restrict__ agg2, int M, int rows_per_block) {
    int f = threadIdx.x;
    long r0 = blockIdx.x * (long)rows_per_block;
    long r1 = r0 + rows_per_block; if (r1 > M) r1 = M;
    float s = 0.f, ss = 0.f;
    for (long r = r0; r < r1; r++) {
        float v = agg2[r * F + f];
        s += v; ss += v * v;
    }
    atomicAdd(&g_bnsum[f], s);
    atomicAdd(&g_bnssq[f], ss);
}

// ---------------- fused BN + LN ----------------
__global__ void bn_ln_final(const float* __restrict__ agg2,
                            const float* __restrict__ bg, const float* __restrict__ bb,
                            const float* __restrict__ lg, const float* __restrict__ lb,
                            float* __restrict__ out, int M) {
    long r = blockIdx.x;
    int  f = threadIdx.x;
    int  lane = f & 31, wid = f >> 5;
    float invM = 1.0f / (float)M;

    float mu  = g_bnsum[f] * invM;
    float var = g_bnssq[f] * invM - mu * mu;
    float v = agg2[r * F + f];
    float y = (v - mu) * rsqrtf(var + EPSV) * bg[f] + bb[f];

    float s = y, ss = y * y;
#pragma unroll
    for (int o = 16; o > 0; o >>= 1) {
        s  += __shfl_xor_sync(0xffffffffu, s,  o);
        ss += __shfl_xor_sync(0xffffffffu, ss, o);
    }
    __shared__ float reds[8], redss[8];
    if (lane == 0) { reds[wid] = s; redss[wid] = ss; }
    __syncthreads();
    if (wid == 0) {
        float a = lane < 8 ? reds[lane]  : 0.f;
        float b = lane < 8 ? redss[lane] : 0.f;
#pragma unroll
        for (int o = 4; o > 0; o >>= 1) {
            a += __shfl_xor_sync(0xffffffffu, a, o);
            b += __shfl_xor_sync(0xffffffffu, b, o);
        }
        if (lane == 0) { reds[0] = a; redss[0] = b; }
    }
    __syncthreads();
    float lmu  = reds[0]  * (1.0f / F);
    float lvar = redss[0] * (1.0f / F) - lmu * lmu;
    out[r * F + f] = (y - lmu) * rsqrtf(lvar + EPSV) * lg[f] + lb[f];
}

// ---------------- launcher ----------------
extern "C" void kernel_launch(void* const* d_in, const int* in_sizes, int n_in,
                              void* d_out, int out_size) {
    const float* x  = (const float*)d_in[0];
    const void*  ei = d_in[1];
    const float* ew = (const float*)d_in[2];
    const float* W1 = (const float*)d_in[3];
    const float* b1 = (const float*)d_in[4];
    const float* W2 = (const float*)d_in[5];
    const float* b2 = (const float*)d_in[6];
    const float* bg = (const float*)d_in[7];
    const float* bb = (const float*)d_in[8];
    const float* lg = (const float*)d_in[9];
    const float* lb = (const float*)d_in[10];
    float* out = (float*)d_out;

    int  n = in_sizes[0] / NFEAT;            // 50000
    long E = in_sizes[1] / 2;                // 800000
    if (E > E_MAX) E = E_MAX;

    float* h1;   cudaGetSymbolAddress((void**)&h1,   g_h1);
    float* h2;   cudaGetSymbolAddress((void**)&h2,   g_h2);
    float* agg2; cudaGetSymbolAddress((void**)&agg2, g_agg2);
    BF16 *xh, *xl, *a1h, *a1l, *w1h, *w1l, *w2h, *w2l;
    cudaGetSymbolAddress((void**)&xh,  g_xh);
    cudaGetSymbolAddress((void**)&xl,  g_xl);
    cudaGetSymbolAddress((void**)&a1h, g_a1h);
    cudaGetSymbolAddress((void**)&a1l, g_a1l);
    cudaGetSymbolAddress((void**)&w1h, g_w1h);
    cudaGetSymbolAddress((void**)&w1l, g_w1l);
    cudaGetSymbolAddress((void**)&w2h, g_w2h);
    cudaGetSymbolAddress((void**)&w2l, g_w2l);

    cudaFuncSetAttribute(gemm_bf16x3,
                         cudaFuncAttributeMaxDynamicSharedMemorySize, GEMM_DSMEM);

    int eb = (int)((E + 255) / 256);
    long x4  = (long)n * NFEAT / 4;
    long w14 = (long)NFEAT * F / 4;
    long w24 = (long)F * F / 4;
    dim3 gg((n + 127) / 128, F / 128);
    int gatherBlocks = (n * 32 + 255) / 256;

    // ---- launches 0-2: converts (gemm1 prereqs) ----
    convert_split<<<(int)((x4 + 255) / 256), 256>>>(x,  xh,  xl,  x4);
    convert_split<<<(int)((w14 + 255) / 256), 256>>>(W1, w1h, w1l, w14);
    convert_split<<<(int)((w24 + 255) / 256), 256>>>(W2, w2h, w2l, w24);

    // ---- launch 3: GEMM1 (ncu capture slot) ----
    gemm_bf16x3<<<gg, 256, GEMM_DSMEM>>>(n, F, NFEAT, xh, xl, w1h, w1l, h1);

    // ---- CSR + degree chain (serial; fork attempt regressed in R13) ----
    detect_zero<<<(n + 255) / 256, 256>>>((const int*)ei, 1024, n);
    histo_deg<<<eb, 256>>>(ei, ew, E);
    scan_offsets<<<1, 1024>>>(n);            // dinv fused in
    scatter_edges<<<eb, 256>>>(ei, ew, E);

    // ---- layer 1 aggregation (writes relu-split bf16 directly) ----
    gather_agg<1><<<gatherBlocks, 256>>>(h1, b1, nullptr, a1h, a1l, n);

    // ---- layer 2 ----
    gemm_bf16x3<<<gg, 256, GEMM_DSMEM>>>(n, F, F, a1h, a1l, w2h, w2l, h2);
    gather_agg<0><<<gatherBlocks, 256>>>(h2, b2, agg2, nullptr, nullptr, n);

    // ---- BN stats + fused BN/LN ----
    const int RPB = 128;
    bn_stats<<<(n + RPB - 1) / RPB, F>>>(agg2, n, RPB);
    bn_ln_final<<<n, F>>>(agg2, bg, bb, lg, lb, out, n);
}